// round 6
// baseline (speedup 1.0000x reference)
#include <cuda_runtime.h>
#include <cuda_bf16.h>
#include <math.h>

// Problem constants
#define BATCH   1024
#define IN_SIZE 512
#define UNITS   512
#define NBASIS  8          // grid_size + order = 5 + 3
#define KDIM    (IN_SIZE * 9)   // 8 bases + 1 silu channel per input feature = 4608

// Scratch (allocation-free rule: __device__ globals)
__device__ float g_A[BATCH * KDIM];   // (1024, 4608) activations: bases + silu
__device__ float g_B[KDIM * UNITS];   // (4608, 512) fused weights: W*scale and scale

// ---------------------------------------------------------------------------
// Kernel 1: build A = [bases(x) | silu(x)] per (b, i)
// Cox-de Boor recursion on uniform knots g_j = -2.2 + 0.4*j (12 knots).
// ---------------------------------------------------------------------------
__global__ void build_A_kernel(const float* __restrict__ x) {
    int idx = blockIdx.x * blockDim.x + threadIdx.x;
    if (idx >= BATCH * IN_SIZE) return;
    float xv = x[idx];

    float g[12];
#pragma unroll
    for (int j = 0; j < 12; j++) g[j] = -2.2f + 0.4f * (float)j;

    float b[11];
#pragma unroll
    for (int j = 0; j < 11; j++)
        b[j] = (xv >= g[j] && xv < g[j + 1]) ? 1.0f : 0.0f;

#pragma unroll
    for (int k = 1; k <= 3; k++) {
#pragma unroll
        for (int j = 0; j < 10; j++) {
            if (j < 11 - k) {
                float left  = (xv - g[j]) / (g[j + k] - g[j]) * b[j];
                float right = (g[j + k + 1] - xv) / (g[j + k + 1] - g[j + 1]) * b[j + 1];
                b[j] = left + right;
            }
        }
    }

    float s = xv / (1.0f + expf(-xv));   // silu

    // idx = bb*512 + i  ->  row offset bb*4608 + i*9 == idx*9
    float* dst = g_A + (size_t)idx * 9;
#pragma unroll
    for (int j = 0; j < 8; j++) dst[j] = b[j];
    dst[8] = s;
}

// ---------------------------------------------------------------------------
// Kernel 2: build fused weight matrix B[(i*9+k), o]
//   k < 8 : spline_kernel[i,k,o] * scale[i,o]
//   k = 8 : scale[i,o]                       (silu channel)
// ---------------------------------------------------------------------------
__global__ void build_B_kernel(const float* __restrict__ W,
                               const float* __restrict__ S) {
    int idx = blockIdx.x * blockDim.x + threadIdx.x;
    if (idx >= KDIM * UNITS) return;
    int o = idx & (UNITS - 1);
    int r = idx >> 9;          // row in [0, 4608)
    int i = r / 9;
    int k = r - i * 9;
    float s = S[(i << 9) + o];
    float v = (k < 8) ? W[((i * 8 + k) << 9) + o] * s : s;
    g_B[idx] = v;
}

// ---------------------------------------------------------------------------
// Kernel 3: GEMM  out[1024,512] = A[1024,4608] @ B[4608,512] + bias
// 64x64 tile, BK=16, 256 threads, 4x4 microtile, register-prefetch pipeline.
// 128 CTAs -> single wave on 148 SMs.
// ---------------------------------------------------------------------------
#define BM 64
#define BN 64
#define BK 16

__global__ __launch_bounds__(256, 1)
void gemm_kernel(const float* __restrict__ bias, float* __restrict__ out) {
    __shared__ float As[BK][BM];
    __shared__ float Bs[BK][BN];

    const int tid = threadIdx.x;
    const int tx = tid & 15;       // M direction (16)
    const int ty = tid >> 4;       // N direction (16)
    const int m0 = blockIdx.y * BM;
    const int n0 = blockIdx.x * BN;

    // global-load assignment: 1 float4 of A and 1 float4 of B per thread/iter
    const int a_row = tid >> 2;          // 0..63
    const int a_kv  = (tid & 3) << 2;    // 0,4,8,12
    const int b_row = tid >> 4;          // 0..15
    const int b_col = (tid & 15) << 2;   // 0..60

    const float* Aptr = g_A + (size_t)(m0 + a_row) * KDIM + a_kv;
    const float* Bptr = g_B + (size_t)b_row * UNITS + n0 + b_col;

    float acc[4][4];
#pragma unroll
    for (int i = 0; i < 4; i++)
#pragma unroll
        for (int j = 0; j < 4; j++) acc[i][j] = 0.0f;

    float4 a_next = *(const float4*)Aptr;
    float4 b_next = *(const float4*)Bptr;

    for (int k0 = 0; k0 < KDIM; k0 += BK) {
        float4 a_cur = a_next;
        float4 b_cur = b_next;
        __syncthreads();   // previous tile fully consumed
        As[a_kv + 0][a_row] = a_cur.x;
        As[a_kv + 1][a_row] = a_cur.y;
        As[a_kv + 2][a_row] = a_cur.z;
        As[a_kv + 3][a_row] = a_cur.w;
        *(float4*)&Bs[b_row][b_col] = b_cur;
        __syncthreads();

        if (k0 + BK < KDIM) {
            a_next = *(const float4*)(Aptr + k0 + BK);
            b_next = *(const float4*)(Bptr + (size_t)(k0 + BK) * UNITS);
        }

#pragma unroll
        for (int k = 0; k < BK; k++) {
            float4 af = *(const float4*)&As[k][tx << 2];
            float4 bf = *(const float4*)&Bs[k][ty << 2];
            float am[4] = {af.x, af.y, af.z, af.w};
            float bn[4] = {bf.x, bf.y, bf.z, bf.w};
#pragma unroll
            for (int i = 0; i < 4; i++)
#pragma unroll
                for (int j = 0; j < 4; j++)
                    acc[i][j] = fmaf(am[i], bn[j], acc[i][j]);
        }
    }

    // epilogue: + bias, write out
    const int nb = n0 + (ty << 2);
    float4 bv = *(const float4*)&bias[nb];
    float bb[4] = {bv.x, bv.y, bv.z, bv.w};
#pragma unroll
    for (int i = 0; i < 4; i++) {
        int m = m0 + (tx << 2) + i;
        float4 r;
        r.x = acc[i][0] + bb[0];
        r.y = acc[i][1] + bb[1];
        r.z = acc[i][2] + bb[2];
        r.w = acc[i][3] + bb[3];
        *(float4*)&out[(size_t)m * UNITS + nb] = r;
    }
}

// ---------------------------------------------------------------------------
extern "C" void kernel_launch(void* const* d_in, const int* in_sizes, int n_in,
                              void* d_out, int out_size) {
    const float* x    = (const float*)d_in[0];  // (1024, 512)
    const float* W    = (const float*)d_in[1];  // (512, 8, 512)
    const float* S    = (const float*)d_in[2];  // (512, 512)
    const float* bias = (const float*)d_in[3];  // (512,)
    float* out = (float*)d_out;                 // (1024, 512)

    build_A_kernel<<<(BATCH * IN_SIZE + 255) / 256, 256>>>(x);
    build_B_kernel<<<(KDIM * UNITS + 255) / 256, 256>>>(W, S);

    dim3 grid(UNITS / BN, BATCH / BM);   // (8, 16) = 128 CTAs
    gemm_kernel<<<grid, 256>>>(bias, out);
}

// round 8
// speedup vs baseline: 2.9141x; 2.9141x over previous
#include <cuda_runtime.h>
#include <cuda_bf16.h>
#include <math.h>
#include <stdint.h>

// ---------------------------------------------------------------------------
// Problem constants
// ---------------------------------------------------------------------------
#define BATCH   1024
#define IN_SIZE 512
#define UNITS   512
#define KDIM    (IN_SIZE * 9)     // 8 spline bases + 1 silu channel = 4608
#define BK      32
#define NKT     (KDIM / BK)       // 144 K-tiles

// Scratch (__device__ globals — allocation-free rule)
__device__ float g_A [BATCH * KDIM];   // (1024, 4608) row-major, K contiguous
__device__ float g_Bt[UNITS * KDIM];   // (512, 4608)  row-major, K contiguous

// ---------------------------------------------------------------------------
// Helpers (arch-baseline PTX only: cp.async / ldmatrix / mma.sync — no tcgen05)
// ---------------------------------------------------------------------------
__device__ __forceinline__ float to_tf32(float f) {
    uint32_t u;
    asm("cvt.rna.tf32.f32 %0, %1;" : "=r"(u) : "f"(f));
    return __uint_as_float(u);
}

__device__ __forceinline__ uint32_t smem_u32(const void* p) {
    uint32_t a;
    asm("{ .reg .u64 t; cvta.to.shared.u64 t, %1; cvt.u32.u64 %0, t; }" : "=r"(a) : "l"(p));
    return a;
}

#define CP_ASYNC16(dst, src) \
    asm volatile("cp.async.cg.shared.global [%0], [%1], 16;" :: "r"(dst), "l"(src) : "memory")
#define CP_COMMIT() asm volatile("cp.async.commit_group;" ::: "memory")
#define CP_WAIT2()  asm volatile("cp.async.wait_group 2;" ::: "memory")

__device__ __forceinline__ void ldsm4(uint32_t* r, uint32_t addr) {
    asm volatile("ldmatrix.sync.aligned.m8n8.x4.shared.b16 {%0,%1,%2,%3}, [%4];"
                 : "=r"(r[0]), "=r"(r[1]), "=r"(r[2]), "=r"(r[3]) : "r"(addr));
}

__device__ __forceinline__ void mma_tf32(float* c, const uint32_t* a, const uint32_t* b) {
    asm volatile("mma.sync.aligned.m16n8k8.row.col.f32.tf32.tf32.f32 "
                 "{%0,%1,%2,%3}, {%4,%5,%6,%7}, {%8,%9}, {%0,%1,%2,%3};"
                 : "+f"(c[0]), "+f"(c[1]), "+f"(c[2]), "+f"(c[3])
                 : "r"(a[0]), "r"(a[1]), "r"(a[2]), "r"(a[3]), "r"(b[0]), "r"(b[1]));
}

// ---------------------------------------------------------------------------
// Kernel 1: build A = [tf32(bases(x)) | tf32(silu(x))], coalesced via smem
// ---------------------------------------------------------------------------
__global__ __launch_bounds__(256) void build_A_kernel(const float* __restrict__ x) {
    __shared__ float sA[256 * 9];
    const int tid = threadIdx.x;
    const int idx = blockIdx.x * 256 + tid;
    const float xv = x[idx];

    float g[12];
#pragma unroll
    for (int j = 0; j < 12; j++) g[j] = -2.2f + 0.4f * (float)j;

    float b[11];
#pragma unroll
    for (int j = 0; j < 11; j++)
        b[j] = (xv >= g[j] && xv < g[j + 1]) ? 1.0f : 0.0f;

    const float r1 = 2.5f, r2 = 1.25f, r3 = 1.0f / 1.2f;
#pragma unroll
    for (int j = 0; j < 10; j++)
        b[j] = (xv - g[j]) * r1 * b[j] + (g[j + 2] - xv) * r1 * b[j + 1];
#pragma unroll
    for (int j = 0; j < 9; j++)
        b[j] = (xv - g[j]) * r2 * b[j] + (g[j + 3] - xv) * r2 * b[j + 1];
#pragma unroll
    for (int j = 0; j < 8; j++)
        b[j] = (xv - g[j]) * r3 * b[j] + (g[j + 4] - xv) * r3 * b[j + 1];

    const float s = __fdividef(xv, 1.0f + __expf(-xv));  // silu

#pragma unroll
    for (int j = 0; j < 8; j++) sA[tid * 9 + j] = to_tf32(b[j]);
    sA[tid * 9 + 8] = to_tf32(s);
    __syncthreads();

    float4* dst = (float4*)(g_A + (size_t)blockIdx.x * 2304);
    const float4* src = (const float4*)sA;
    for (int t = tid; t < 576; t += 256) dst[t] = src[t];
}

// ---------------------------------------------------------------------------
// Kernel 2: build Bt[o, i*9+k] = tf32( k<8 ? W[i,k,o]*S[i,o] : S[i,o] )
// ---------------------------------------------------------------------------
__global__ __launch_bounds__(256) void build_Bt_kernel(const float* __restrict__ W,
                                                       const float* __restrict__ S) {
    __shared__ float tile[32][33];
    const int tx = threadIdx.x & 31;
    const int ty = threadIdx.x >> 5;
    const int r0 = blockIdx.x * 32;   // K dim
    const int o0 = blockIdx.y * 32;   // units dim

#pragma unroll
    for (int yy = ty; yy < 32; yy += 8) {
        int sr = r0 + yy;
        int i = sr / 9;
        int k = sr - i * 9;
        int o = o0 + tx;
        float s = S[(i << 9) + o];
        float v = (k < 8) ? W[((i * 8 + k) << 9) + o] * s : s;
        tile[yy][tx] = to_tf32(v);
    }
    __syncthreads();
#pragma unroll
    for (int yy = ty; yy < 32; yy += 8)
        g_Bt[(size_t)(o0 + yy) * KDIM + r0 + tx] = tile[tx][yy];
}

// ---------------------------------------------------------------------------
// Kernel 3: tf32 mma.sync GEMM  out[1024,512] = A @ Bt^T + bias
// CTA 64x64, BK=32, 4-stage cp.async, 128 threads = 4 warps (2x2, 32x32/warp).
// Smem rows padded to 144B -> conflict-free ldmatrix phases.
// ---------------------------------------------------------------------------
#define ROWB     144                   // 32 floats (128B) + 16B pad
#define TILEB    (64 * ROWB)           // 9216 B per operand tile
#define STAGEB   (2 * TILEB)           // 18432 B (A then B)
#define NSTAGES  4
#define SMEM_TOTAL (NSTAGES * STAGEB)  // 73728 B

__global__ __launch_bounds__(128, 1)
void gemm_mma_kernel(const float* __restrict__ bias, float* __restrict__ out) {
    extern __shared__ char smem[];
    const uint32_t sb = smem_u32(smem);
    const int tid  = threadIdx.x;
    const int lane = tid & 31;
    const int warp = tid >> 5;
    const int wm = warp & 1;           // 0..1  (rows 32*wm)
    const int wn = warp >> 1;          // 0..1  (cols 32*wn)
    const int m0 = blockIdx.y * 64;
    const int n0 = blockIdx.x * 64;

    // ---- cp.async assignments: 4 A-chunks + 4 B-chunks of 16B per thread/stage
    const char* gaddrA[4];
    const char* gaddrB[4];
    uint32_t soff[4];
#pragma unroll
    for (int j = 0; j < 4; j++) {
        int q = tid + 128 * j;         // 0..511
        int r = q >> 3;                // row 0..63
        int c = q & 7;                 // 16B chunk 0..7
        soff[j]   = (uint32_t)(r * ROWB + c * 16);
        gaddrA[j] = (const char*)(g_A  + (size_t)(m0 + r) * KDIM) + c * 16;
        gaddrB[j] = (const char*)(g_Bt + (size_t)(n0 + r) * KDIM) + c * 16;
    }

    // ---- ldmatrix per-lane base offsets (within a stage) ----
    // A x4 blocks: (r0-7,k0-3)(r8-15,k0-3)(r0-7,k4-7)(r8-15,k4-7) per 16-row m-tile
    uint32_t aoff[2];
#pragma unroll
    for (int mt = 0; mt < 2; mt++) {
        int rowA = 32 * wm + 16 * mt + (lane & 7) + 8 * ((lane >> 3) & 1);
        aoff[mt] = (uint32_t)(rowA * ROWB + 16 * (lane >> 4));
    }
    // B x4 blocks: (n0-7,klo)(n0-7,khi)(n8-15,klo)(n8-15,khi) per 16-col pair
    uint32_t boff[2];
#pragma unroll
    for (int p = 0; p < 2; p++) {
        int rowB = 32 * wn + 16 * p + (lane & 7) + 8 * (lane >> 4);
        boff[p] = (uint32_t)(TILEB + rowB * ROWB + 16 * ((lane >> 3) & 1));
    }

    float c[2][4][4];
#pragma unroll
    for (int i = 0; i < 2; i++)
#pragma unroll
        for (int j = 0; j < 4; j++)
#pragma unroll
            for (int q = 0; q < 4; q++) c[i][j][q] = 0.0f;

    // ---- prefetch first 3 stages ----
#pragma unroll
    for (int s = 0; s < 3; s++) {
        const uint32_t st = sb + s * STAGEB;
        const size_t kb = (size_t)s * BK * 4;
#pragma unroll
        for (int j = 0; j < 4; j++) CP_ASYNC16(st + soff[j], gaddrA[j] + kb);
#pragma unroll
        for (int j = 0; j < 4; j++) CP_ASYNC16(st + TILEB + soff[j], gaddrB[j] + kb);
        CP_COMMIT();
    }

    for (int kt = 0; kt < NKT; kt++) {
        CP_WAIT2();
        __syncthreads();

        // issue loads for kt+3 into stage (kt+3)&3  (== (kt-1)&3, consumed last iter)
        if (kt + 3 < NKT) {
            const uint32_t st = sb + ((kt + 3) & 3) * STAGEB;
            const size_t kb = (size_t)(kt + 3) * BK * 4;
#pragma unroll
            for (int j = 0; j < 4; j++) CP_ASYNC16(st + soff[j], gaddrA[j] + kb);
#pragma unroll
            for (int j = 0; j < 4; j++) CP_ASYNC16(st + TILEB + soff[j], gaddrB[j] + kb);
        }
        CP_COMMIT();   // always commit (possibly empty) to keep group count in lockstep

        // ---- compute stage kt&3 : 4 k-steps of 8 ----
        const uint32_t st = sb + (kt & 3) * STAGEB;
#pragma unroll
        for (int ks = 0; ks < 4; ks++) {
            uint32_t a[2][4], bf[2][4];
            ldsm4(a[0],  st + aoff[0] + 32 * ks);
            ldsm4(a[1],  st + aoff[1] + 32 * ks);
            ldsm4(bf[0], st + boff[0] + 32 * ks);
            ldsm4(bf[1], st + boff[1] + 32 * ks);
#pragma unroll
            for (int mt = 0; mt < 2; mt++) {
#pragma unroll
                for (int p = 0; p < 2; p++) {
                    mma_tf32(c[mt][2 * p],     a[mt], &bf[p][0]);   // b0,b1
                    mma_tf32(c[mt][2 * p + 1], a[mt], &bf[p][2]);   // b0,b1 of nt hi
                }
            }
        }
    }

    // ---- epilogue: + bias, write fp32 ----
    const int mb = m0 + 32 * wm + (lane >> 2);
    const int nb = n0 + 32 * wn + 2 * (lane & 3);
#pragma unroll
    for (int mt = 0; mt < 2; mt++) {
#pragma unroll
        for (int nt = 0; nt < 4; nt++) {
            const int col = nb + 8 * nt;
            const float b0 = bias[col], b1 = bias[col + 1];
            const int r0 = mb + 16 * mt;
            float2 v0 = make_float2(c[mt][nt][0] + b0, c[mt][nt][1] + b1);
            float2 v1 = make_float2(c[mt][nt][2] + b0, c[mt][nt][3] + b1);
            *(float2*)&out[(size_t)r0 * UNITS + col]       = v0;
            *(float2*)&out[(size_t)(r0 + 8) * UNITS + col] = v1;
        }
    }
}

// ---------------------------------------------------------------------------
extern "C" void kernel_launch(void* const* d_in, const int* in_sizes, int n_in,
                              void* d_out, int out_size) {
    const float* x    = (const float*)d_in[0];  // (1024, 512)
    const float* W    = (const float*)d_in[1];  // (512, 8, 512)
    const float* S    = (const float*)d_in[2];  // (512, 512)
    const float* bias = (const float*)d_in[3];  // (512,)
    float* out = (float*)d_out;                 // (1024, 512)

    cudaFuncSetAttribute(gemm_mma_kernel,
                         cudaFuncAttributeMaxDynamicSharedMemorySize, SMEM_TOTAL);

    build_A_kernel<<<(BATCH * IN_SIZE) / 256, 256>>>(x);

    dim3 gb(KDIM / 32, UNITS / 32);             // (144, 16)
    build_Bt_kernel<<<gb, 256>>>(W, S);

    dim3 gg(UNITS / 64, BATCH / 64);            // (8, 16) = 128 CTAs
    gemm_mma_kernel<<<gg, 128, SMEM_TOTAL>>>(bias, out);
}